// round 11
// baseline (speedup 1.0000x reference)
#include <cuda_runtime.h>
#include <cuda_fp16.h>

#define RR 128
#define BASIS 9
#define DATA_DIM 28
#define NUM_STEPS 256
#define STEP_SIZE 0.001f
#define BG 1.0f

#define NVOX (RR*RR*RR)           // 2097152
// 32 halves per voxel, interleaved for HFMA2 (R6 layout):
//  halves 0..17 : (c0_j, c1_j) pairs, j = 0..8
//  halves 18..26: c2_0 .. c2_8
//  half  27     : 0
//  half  28     : sigma
//  halves 29..31: 0
__device__ uint4 g_grid[NVOX * 4];     // 128 MiB, 64B-aligned records

// ---------------------------------------------------------------------------
// Conversion via smem staging (R10 version)
// ---------------------------------------------------------------------------
__global__ void __launch_bounds__(256)
convert_kernel(const float* __restrict__ tree)
{
    __shared__ float sm[64 * DATA_DIM];
    int tid = threadIdx.x;
    long long v0 = (long long)blockIdx.x * 64;

    const float4* src4 = reinterpret_cast<const float4*>(tree) + v0 * 7;
    float4* sm4 = reinterpret_cast<float4*>(sm);
    #pragma unroll
    for (int k = tid; k < 448; k += 256)
        sm4[k] = __ldg(src4 + k);
    __syncthreads();

    int vl = tid >> 2;
    int q  = tid & 3;
    const float* f = sm + vl * DATA_DIM;

    __half h[8];
    if (q == 0) {
        h[0]=__float2half_rn(f[0]);  h[1]=__float2half_rn(f[9]);
        h[2]=__float2half_rn(f[1]);  h[3]=__float2half_rn(f[10]);
        h[4]=__float2half_rn(f[2]);  h[5]=__float2half_rn(f[11]);
        h[6]=__float2half_rn(f[3]);  h[7]=__float2half_rn(f[12]);
    } else if (q == 1) {
        h[0]=__float2half_rn(f[4]);  h[1]=__float2half_rn(f[13]);
        h[2]=__float2half_rn(f[5]);  h[3]=__float2half_rn(f[14]);
        h[4]=__float2half_rn(f[6]);  h[5]=__float2half_rn(f[15]);
        h[6]=__float2half_rn(f[7]);  h[7]=__float2half_rn(f[16]);
    } else if (q == 2) {
        h[0]=__float2half_rn(f[8]);  h[1]=__float2half_rn(f[17]);
        h[2]=__float2half_rn(f[18]); h[3]=__float2half_rn(f[19]);
        h[4]=__float2half_rn(f[20]); h[5]=__float2half_rn(f[21]);
        h[6]=__float2half_rn(f[22]); h[7]=__float2half_rn(f[23]);
    } else {
        h[0]=__float2half_rn(f[24]); h[1]=__float2half_rn(f[25]);
        h[2]=__float2half_rn(f[26]); h[3]=__float2half_rn(0.0f);
        h[4]=__float2half_rn(f[27]); h[5]=__float2half_rn(0.0f);
        h[6]=__float2half_rn(0.0f);  h[7]=__float2half_rn(0.0f);
    }
    g_grid[v0 * 4 + tid] = *reinterpret_cast<uint4*>(h);
}

__device__ __forceinline__ uint4 shfl_xor_u4(unsigned mask, uint4 v)
{
    uint4 r;
    r.x = __shfl_xor_sync(mask, v.x, 1);
    r.y = __shfl_xor_sync(mask, v.y, 1);
    r.z = __shfl_xor_sync(mask, v.z, 1);
    r.w = __shfl_xor_sync(mask, v.w, 1);
    return r;
}

// ---------------------------------------------------------------------------
// Renderer: 1 thread = 1 ray; lane pairs cooperate on LOADS only.
// Shading is bit-identical to the R10 kernel.
// ---------------------------------------------------------------------------
__global__ void __launch_bounds__(128)
volrend_kernel(const float* __restrict__ origins,
               const float* __restrict__ dirs,
               const float* __restrict__ viewdirs,
               const float* __restrict__ invradius,
               float* __restrict__ out,
               int nb)
{
    int i = blockIdx.x * blockDim.x + threadIdx.x;
    int p = i & 1;
    unsigned pmask = 3u << ((threadIdx.x & 31) & ~1);
    bool ray_ok = (i < nb);
    int ii = ray_ok ? i : (nb > 0 ? nb - 1 : 0);

    float ox = origins[3*ii+0], oy = origins[3*ii+1], oz = origins[3*ii+2];
    float dx = dirs[3*ii+0],    dy = dirs[3*ii+1],    dz = dirs[3*ii+2];
    float inv_norm = rsqrtf(dx*dx + dy*dy + dz*dz);
    dx *= inv_norm; dy *= inv_norm; dz *= inv_norm;

    float vx = viewdirs[3*ii+0], vy = viewdirs[3*ii+1], vz = viewdirs[3*ii+2];

    float sh[BASIS];
    sh[0] =  0.28209479177387814f;
    sh[1] = -0.4886025119029199f * vy;
    sh[2] =  0.4886025119029199f * vz;
    sh[3] = -0.4886025119029199f * vx;
    sh[4] =  1.0925484305920792f * vx * vy;
    sh[5] = -1.0925484305920792f * vy * vz;
    sh[6] =  0.31539156525252005f * (2.0f*vz*vz - vx*vx - vy*vy);
    sh[7] = -1.0925484305920792f * vx * vz;
    sh[8] =  0.5462742152960396f * (vx*vx - vy*vy);

    __half2 s01[BASIS];
    #pragma unroll
    for (int j = 0; j < BASIS; ++j) s01[j] = __floats2half2_rn(sh[j], sh[j]);
    __half2 s2[5];
    s2[0] = __floats2half2_rn(sh[0], sh[1]);
    s2[1] = __floats2half2_rn(sh[2], sh[3]);
    s2[2] = __floats2half2_rn(sh[4], sh[5]);
    s2[3] = __floats2half2_rn(sh[6], sh[7]);
    s2[4] = __floats2half2_rn(sh[8], 0.0f);

    float idrx = 1.0f / (dx + 1e-9f);
    float idry = 1.0f / (dy + 1e-9f);
    float idrz = 1.0f / (dz + 1e-9f);

    float t1x = -ox * idrx, t2x = t1x + idrx;
    float t1y = -oy * idry, t2y = t1y + idry;
    float t1z = -oz * idrz, t2z = t1z + idrz;
    float tmin = fmaxf(fmaxf(fminf(t1x,t2x), fminf(t1y,t2y)), fminf(t1z,t2z));
    tmin = fmaxf(tmin, 0.0f);
    float tmax = fminf(fminf(fmaxf(t1x,t2x), fmaxf(t1y,t2y)), fmaxf(t1z,t2z));
    tmax = fminf(tmax, 1e9f);

    float irx = invradius[0], iry = invradius[1], irz = invradius[2];
    float dsx = dx / irx, dsy = dy / iry, dsz = dz / irz;
    float delta_scale = sqrtf(dsx*dsx + dsy*dsy + dsz*dsz);

    float oxR = ox * (float)RR, oyR = oy * (float)RR, ozR = oz * (float)RR;
    float dxR = dx * (float)RR, dyR = dy * (float)RR, dzR = dz * (float)RR;

    float t = tmin;
    float light = 1.0f;
    float out0 = 0.0f, out1 = 0.0f, out2 = 0.0f;
    const float cube_sz = 1.0f / (float)RR;

    #define GEOM(tt, dt_o, flat_o)                                             \
    {                                                                          \
        float px = fmaf((tt), dxR, oxR);                                       \
        float py = fmaf((tt), dyR, oyR);                                       \
        float pz = fmaf((tt), dzR, ozR);                                       \
        float fx = fminf(fmaxf(floorf(px), 0.0f), (float)(RR-1));              \
        float fy = fminf(fmaxf(floorf(py), 0.0f), (float)(RR-1));              \
        float fz = fminf(fmaxf(floorf(pz), 0.0f), (float)(RR-1));              \
        (flat_o) = (int)fmaf(fx, 16384.0f, fmaf(fy, 128.0f, fz));              \
        float cx = px - fx, cy = py - fy, cz = pz - fz;                        \
        float u1x = -cx * idrx, u2x = u1x + idrx;                              \
        float u1y = -cy * idry, u2y = u1y + idry;                              \
        float u1z = -cz * idrz, u2z = u1z + idrz;                              \
        float s0 = fmaxf(fmaxf(fminf(u1x,u2x), fminf(u1y,u2y)), fminf(u1z,u2z)); \
        s0 = fmaxf(s0, 0.0f);                                                  \
        float s1 = fminf(fminf(fmaxf(u1x,u2x), fmaxf(u1y,u2y)), fmaxf(u1z,u2z)); \
        s1 = fminf(s1, 1e9f);                                                  \
        (dt_o) = (s1 - s0) * cube_sz + STEP_SIZE;                              \
    }

    // Exchange (flat|valid), then issue pair-merged loads of chunk {2p, 2p+1}
    // of record A (even lane's ray) and record B (odd lane's ray).
    #define PAIR_PREFETCH(flat_v, valid_v)                                     \
    {                                                                          \
        unsigned pk = (unsigned)(flat_v) | ((valid_v) ? 0x80000000u : 0u);     \
        unsigned po = __shfl_xor_sync(pmask, pk, 1);                           \
        unsigned kA = p ? po : pk;                                             \
        unsigned kB = p ? pk : po;                                             \
        if (kA & 0x80000000u) {                                                \
            const uint4* bA = g_grid + (size_t)(kA & 0x7FFFFFFFu) * 4 + 2*p;   \
            pA0 = __ldg(bA); pA1 = __ldg(bA + 1);                              \
        }                                                                      \
        if (kB & 0x80000000u) {                                                \
            const uint4* bB = g_grid + (size_t)(kB & 0x7FFFFFFFu) * 4 + 2*p;   \
            pB0 = __ldg(bB); pB1 = __ldg(bB + 1);                              \
        }                                                                      \
        pair_live = ((kA | kB) & 0x80000000u) != 0;                            \
    }

    bool valid = ray_ok && (tmin < tmax);
    float dt_cur = 0.0f;
    int flat_cur = 0;
    if (valid) GEOM(t, dt_cur, flat_cur);

    uint4 pA0 = make_uint4(0,0,0,0), pA1 = pA0, pB0 = pA0, pB1 = pA0;
    bool pair_live;
    PAIR_PREFETCH(flat_cur, valid);

    if (pair_live) {
        #pragma unroll 1
        for (int s = 0; s < NUM_STEPS; ++s) {
            // Reassemble own record from the pair's prefetched halves.
            uint4 sA0 = shfl_xor_u4(pmask, pA0);
            uint4 sA1 = shfl_xor_u4(pmask, pA1);
            uint4 sB0 = shfl_xor_u4(pmask, pB0);
            uint4 sB1 = shfl_xor_u4(pmask, pB1);
            // even (p=0), own record = A: chunks {0,1}=pA0,pA1; {2,3}=sA0,sA1
            // odd  (p=1), own record = B: chunks {0,1}=sB0,sB1; {2,3}=pB0,pB1
            uint4 a0 = p ? sB0 : pA0;
            uint4 a1 = p ? sB1 : pA1;
            uint4 a2 = p ? pB0 : sA0;
            uint4 a3 = p ? pB1 : sA1;
            bool cur_valid = valid;
            float dt = dt_cur;

            // Next-step geometry + pair-merged prefetch
            float t_new = t + dt;
            bool more = cur_valid && (t_new < tmax) && (s + 1 < NUM_STEPS);
            float dt_next = 0.0f;
            int flat_next = 0;
            if (more) GEOM(t_new, dt_next, flat_next);
            PAIR_PREFETCH(flat_next, more);

            if (cur_valid) {
                // Shade — identical to R10
                __half2 v[16];
                *reinterpret_cast<uint4*>(v +  0) = a0;
                *reinterpret_cast<uint4*>(v +  4) = a1;
                *reinterpret_cast<uint4*>(v +  8) = a2;
                *reinterpret_cast<uint4*>(v + 12) = a3;

                __half2 acc01 = __hmul2(s01[0], v[0]);
                #pragma unroll
                for (int j = 1; j < BASIS; ++j)
                    acc01 = __hfma2(s01[j], v[j], acc01);
                __half2 acc2 = __hmul2(s2[0], v[9]);
                #pragma unroll
                for (int k = 1; k < 5; ++k)
                    acc2 = __hfma2(s2[k], v[9 + k], acc2);

                float2 c01 = __half22float2(acc01);
                float2 c2p = __half22float2(acc2);
                float c2 = c2p.x + c2p.y;

                float sigma = fmaxf(__half2float(__low2half(v[14])), 0.0f);
                float att = __expf(-dt * sigma * delta_scale);
                float weight = light * (1.0f - att);

                float r0 = __fdividef(1.0f, 1.0f + __expf(-c01.x));
                float r1 = __fdividef(1.0f, 1.0f + __expf(-c01.y));
                float r2 = __fdividef(1.0f, 1.0f + __expf(-c2));

                out0 = fmaf(weight, r0, out0);
                out1 = fmaf(weight, r1, out1);
                out2 = fmaf(weight, r2, out2);
                light *= att;
            }

            t = t_new;
            dt_cur = dt_next;
            valid = more;
            if (!pair_live) break;   // pair-uniform condition
        }
    }
    #undef PAIR_PREFETCH
    #undef GEOM

    if (ray_ok) {
        out[3*i+0] = out0 + light * BG;
        out[3*i+1] = out1 + light * BG;
        out[3*i+2] = out2 + light * BG;
    }
}

extern "C" void kernel_launch(void* const* d_in, const int* in_sizes, int n_in,
                              void* d_out, int out_size)
{
    const float* tree      = (const float*)d_in[0];
    const float* origins   = (const float*)d_in[1];
    const float* dirs      = (const float*)d_in[2];
    const float* viewdirs  = (const float*)d_in[3];
    const float* invradius = (const float*)d_in[4];
    float* out = (float*)d_out;

    int nb = in_sizes[1] / 3;

    convert_kernel<<<NVOX / 64, 256>>>(tree);

    int threads = 128;
    int blocks = (nb + threads - 1) / threads;
    volrend_kernel<<<blocks, threads>>>(origins, dirs, viewdirs, invradius, out, nb);
}

// round 12
// speedup vs baseline: 2.0038x; 2.0038x over previous
#include <cuda_runtime.h>
#include <cuda_fp16.h>

#define RR 128
#define BASIS 9
#define DATA_DIM 28
#define NUM_STEPS 256
#define STEP_SIZE 0.001f
#define BG 1.0f

#define NVOX (RR*RR*RR)           // 2097152
// 32 halves per voxel, interleaved for HFMA2 (R6 layout):
//  halves 0..17 : (c0_j, c1_j) pairs, j = 0..8
//  halves 18..26: c2_0 .. c2_8
//  half  27     : 0
//  half  28     : sigma
//  halves 29..31: 0
__device__ __align__(64) uint4 g_grid[NVOX * 4];   // 128 MiB, 64B records

// 256-bit load (Blackwell): one LDG.E.256 pulls 32B per lane.
__device__ __forceinline__ void ldg256(const uint4* p, uint4& a, uint4& b)
{
    asm volatile("ld.global.nc.v8.b32 {%0,%1,%2,%3,%4,%5,%6,%7}, [%8];"
        : "=r"(a.x), "=r"(a.y), "=r"(a.z), "=r"(a.w),
          "=r"(b.x), "=r"(b.y), "=r"(b.z), "=r"(b.w)
        : "l"(p));
}

// ---------------------------------------------------------------------------
// Conversion via smem staging (R10 version)
// ---------------------------------------------------------------------------
__global__ void __launch_bounds__(256)
convert_kernel(const float* __restrict__ tree)
{
    __shared__ float sm[64 * DATA_DIM];
    int tid = threadIdx.x;
    long long v0 = (long long)blockIdx.x * 64;

    const float4* src4 = reinterpret_cast<const float4*>(tree) + v0 * 7;
    float4* sm4 = reinterpret_cast<float4*>(sm);
    #pragma unroll
    for (int k = tid; k < 448; k += 256)
        sm4[k] = __ldg(src4 + k);
    __syncthreads();

    int vl = tid >> 2;
    int q  = tid & 3;
    const float* f = sm + vl * DATA_DIM;

    __half h[8];
    if (q == 0) {
        h[0]=__float2half_rn(f[0]);  h[1]=__float2half_rn(f[9]);
        h[2]=__float2half_rn(f[1]);  h[3]=__float2half_rn(f[10]);
        h[4]=__float2half_rn(f[2]);  h[5]=__float2half_rn(f[11]);
        h[6]=__float2half_rn(f[3]);  h[7]=__float2half_rn(f[12]);
    } else if (q == 1) {
        h[0]=__float2half_rn(f[4]);  h[1]=__float2half_rn(f[13]);
        h[2]=__float2half_rn(f[5]);  h[3]=__float2half_rn(f[14]);
        h[4]=__float2half_rn(f[6]);  h[5]=__float2half_rn(f[15]);
        h[6]=__float2half_rn(f[7]);  h[7]=__float2half_rn(f[16]);
    } else if (q == 2) {
        h[0]=__float2half_rn(f[8]);  h[1]=__float2half_rn(f[17]);
        h[2]=__float2half_rn(f[18]); h[3]=__float2half_rn(f[19]);
        h[4]=__float2half_rn(f[20]); h[5]=__float2half_rn(f[21]);
        h[6]=__float2half_rn(f[22]); h[7]=__float2half_rn(f[23]);
    } else {
        h[0]=__float2half_rn(f[24]); h[1]=__float2half_rn(f[25]);
        h[2]=__float2half_rn(f[26]); h[3]=__float2half_rn(0.0f);
        h[4]=__float2half_rn(f[27]); h[5]=__float2half_rn(0.0f);
        h[6]=__float2half_rn(0.0f);  h[7]=__float2half_rn(0.0f);
    }
    g_grid[v0 * 4 + tid] = *reinterpret_cast<uint4*>(h);
}

// ---------------------------------------------------------------------------
// Main renderer: R10 structure, 256-bit gathers
// ---------------------------------------------------------------------------
__global__ void __launch_bounds__(128, 9)
volrend_kernel(const float* __restrict__ origins,
               const float* __restrict__ dirs,
               const float* __restrict__ viewdirs,
               const float* __restrict__ invradius,
               float* __restrict__ out,
               int nb)
{
    int i = blockIdx.x * blockDim.x + threadIdx.x;
    if (i >= nb) return;

    float ox = origins[3*i+0], oy = origins[3*i+1], oz = origins[3*i+2];
    float dx = dirs[3*i+0],    dy = dirs[3*i+1],    dz = dirs[3*i+2];
    float inv_norm = rsqrtf(dx*dx + dy*dy + dz*dz);
    dx *= inv_norm; dy *= inv_norm; dz *= inv_norm;

    float vx = viewdirs[3*i+0], vy = viewdirs[3*i+1], vz = viewdirs[3*i+2];

    float sh[BASIS];
    sh[0] =  0.28209479177387814f;
    sh[1] = -0.4886025119029199f * vy;
    sh[2] =  0.4886025119029199f * vz;
    sh[3] = -0.4886025119029199f * vx;
    sh[4] =  1.0925484305920792f * vx * vy;
    sh[5] = -1.0925484305920792f * vy * vz;
    sh[6] =  0.31539156525252005f * (2.0f*vz*vz - vx*vx - vy*vy);
    sh[7] = -1.0925484305920792f * vx * vz;
    sh[8] =  0.5462742152960396f * (vx*vx - vy*vy);

    // HFMA2 operand packs
    __half2 s01[BASIS];
    #pragma unroll
    for (int j = 0; j < BASIS; ++j) s01[j] = __floats2half2_rn(sh[j], sh[j]);
    __half2 s2[5];
    s2[0] = __floats2half2_rn(sh[0], sh[1]);
    s2[1] = __floats2half2_rn(sh[2], sh[3]);
    s2[2] = __floats2half2_rn(sh[4], sh[5]);
    s2[3] = __floats2half2_rn(sh[6], sh[7]);
    s2[4] = __floats2half2_rn(sh[8], 0.0f);

    float idrx = 1.0f / (dx + 1e-9f);
    float idry = 1.0f / (dy + 1e-9f);
    float idrz = 1.0f / (dz + 1e-9f);

    float t1x = -ox * idrx, t2x = t1x + idrx;
    float t1y = -oy * idry, t2y = t1y + idry;
    float t1z = -oz * idrz, t2z = t1z + idrz;
    float tmin = fmaxf(fmaxf(fminf(t1x,t2x), fminf(t1y,t2y)), fminf(t1z,t2z));
    tmin = fmaxf(tmin, 0.0f);
    float tmax = fminf(fminf(fmaxf(t1x,t2x), fmaxf(t1y,t2y)), fmaxf(t1z,t2z));
    tmax = fminf(tmax, 1e9f);

    float irx = invradius[0], iry = invradius[1], irz = invradius[2];
    float dsx = dx / irx, dsy = dy / iry, dsz = dz / irz;
    float delta_scale = sqrtf(dsx*dsx + dsy*dsy + dsz*dsz);

    float oxR = ox * (float)RR, oyR = oy * (float)RR, ozR = oz * (float)RR;
    float dxR = dx * (float)RR, dyR = dy * (float)RR, dzR = dz * (float)RR;

    float t = tmin;
    float light = 1.0f;
    float out0 = 0.0f, out1 = 0.0f, out2 = 0.0f;
    const float cube_sz = 1.0f / (float)RR;

    #define GEOM(tt, dt_o, vp_o)                                               \
    {                                                                          \
        float px = fmaf((tt), dxR, oxR);                                       \
        float py = fmaf((tt), dyR, oyR);                                       \
        float pz = fmaf((tt), dzR, ozR);                                       \
        float fx = fminf(fmaxf(floorf(px), 0.0f), (float)(RR-1));              \
        float fy = fminf(fmaxf(floorf(py), 0.0f), (float)(RR-1));              \
        float fz = fminf(fmaxf(floorf(pz), 0.0f), (float)(RR-1));              \
        int flat = (int)fmaf(fx, 16384.0f, fmaf(fy, 128.0f, fz));              \
        (vp_o) = g_grid + (size_t)flat * 4;                                    \
        float cx = px - fx, cy = py - fy, cz = pz - fz;                        \
        float u1x = -cx * idrx, u2x = u1x + idrx;                              \
        float u1y = -cy * idry, u2y = u1y + idry;                              \
        float u1z = -cz * idrz, u2z = u1z + idrz;                              \
        float s0 = fmaxf(fmaxf(fminf(u1x,u2x), fminf(u1y,u2y)), fminf(u1z,u2z)); \
        s0 = fmaxf(s0, 0.0f);                                                  \
        float s1 = fminf(fminf(fmaxf(u1x,u2x), fmaxf(u1y,u2y)), fmaxf(u1z,u2z)); \
        s1 = fminf(s1, 1e9f);                                                  \
        (dt_o) = (s1 - s0) * cube_sz + STEP_SIZE;                              \
    }

    if (tmin < tmax) {
        float dt_cur;
        const uint4* vp;
        GEOM(t, dt_cur, vp);
        uint4 b0, b1, b2, b3;
        ldg256(vp,     b0, b1);
        ldg256(vp + 2, b2, b3);

        #pragma unroll 1
        for (int s = 0; s < NUM_STEPS; ++s) {
            uint4 a0 = b0, a1 = b1, a2 = b2, a3 = b3;
            float dt = dt_cur;

            // Prefetch next step before shading
            float t_new = t + dt;
            bool more = (t_new < tmax) && (s + 1 < NUM_STEPS);
            float dt_next = 0.0f;
            if (more) {
                const uint4* vpn;
                GEOM(t_new, dt_next, vpn);
                ldg256(vpn,     b0, b1);
                ldg256(vpn + 2, b2, b3);
            }

            // Shade: half2 SIMD dot products
            __half2 v[16];
            *reinterpret_cast<uint4*>(v +  0) = a0;
            *reinterpret_cast<uint4*>(v +  4) = a1;
            *reinterpret_cast<uint4*>(v +  8) = a2;
            *reinterpret_cast<uint4*>(v + 12) = a3;

            __half2 acc01 = __hmul2(s01[0], v[0]);
            #pragma unroll
            for (int j = 1; j < BASIS; ++j)
                acc01 = __hfma2(s01[j], v[j], acc01);
            __half2 acc2 = __hmul2(s2[0], v[9]);
            #pragma unroll
            for (int k = 1; k < 5; ++k)
                acc2 = __hfma2(s2[k], v[9 + k], acc2);

            float2 c01 = __half22float2(acc01);
            float2 c2p = __half22float2(acc2);
            float c2 = c2p.x + c2p.y;

            float sigma = fmaxf(__half2float(__low2half(v[14])), 0.0f);
            float att = __expf(-dt * sigma * delta_scale);
            float weight = light * (1.0f - att);

            float r0 = __fdividef(1.0f, 1.0f + __expf(-c01.x));
            float r1 = __fdividef(1.0f, 1.0f + __expf(-c01.y));
            float r2 = __fdividef(1.0f, 1.0f + __expf(-c2));

            out0 = fmaf(weight, r0, out0);
            out1 = fmaf(weight, r1, out1);
            out2 = fmaf(weight, r2, out2);
            light *= att;

            t = t_new;
            dt_cur = dt_next;
            if (!more) break;
        }
    }
    #undef GEOM

    out[3*i+0] = out0 + light * BG;
    out[3*i+1] = out1 + light * BG;
    out[3*i+2] = out2 + light * BG;
}

extern "C" void kernel_launch(void* const* d_in, const int* in_sizes, int n_in,
                              void* d_out, int out_size)
{
    const float* tree      = (const float*)d_in[0];
    const float* origins   = (const float*)d_in[1];
    const float* dirs      = (const float*)d_in[2];
    const float* viewdirs  = (const float*)d_in[3];
    const float* invradius = (const float*)d_in[4];
    float* out = (float*)d_out;

    int nb = in_sizes[1] / 3;

    convert_kernel<<<NVOX / 64, 256>>>(tree);

    int threads = 128;
    int blocks = (nb + threads - 1) / threads;
    volrend_kernel<<<blocks, threads>>>(origins, dirs, viewdirs, invradius, out, nb);
}